// round 14
// baseline (speedup 1.0000x reference)
#include <cuda_runtime.h>
#include <cuda_bf16.h>
#include <math.h>
#include <stdint.h>

// Problem constants
#define Bn 64
#define Un 1024
#define Hn 16
#define Mn 512
#define Dn 4
#define NSLOT 513
#define NRr 8208
#define NWw 8192
#define U4 256
#define MCH 32
#define NCH 16
#define SLP 520
#define BHR 512
#define BSTR 524288
#define NV4 16384
#define LOGZ (Bn*Hn*SLP)
#define KZ 8                 // K-split factor for Wk GEMM

// -------- scratch --------
__device__ __nv_bfloat16 g_memh[Bn*Mn*Un];
__device__ float g_part [Bn*NCH*Un];
__device__ float g_S    [Bn*Un];
__device__ float g_slot [Bn*Un];
__device__ float g_state[Bn*Un];
__device__ float g_rlogT[2*LOGZ];
__device__ float g_rwT  [Bn*Hn*SLP];
__device__ float g_wlogT[2*LOGZ];
__device__ float g_cmean[Bn*Hn];
__device__ float g_read [Bn*Un];
__device__ float g_nv   [4*Bn*Un];
__device__ float g_kpart[KZ*Bn*Un];
__device__ float g_A    [Bn*Hn*BHR];
__device__ float g_wA   [Bn*Hn*BHR];
__device__ float g_B    [4*Bn*Hn*BHR];
__device__ float g_sB   [4*Bn*Hn];

// -------- helpers --------
static __device__ __forceinline__ uint32_t smem_u32(const void* p) {
    return (uint32_t)__cvta_generic_to_shared(p);
}
static __device__ __forceinline__ uint32_t pk2(float a, float b) {
    __nv_bfloat162 t = __floats2bfloat162_rn(a, b);
    return *reinterpret_cast<uint32_t*>(&t);
}
static __device__ __forceinline__ float4 bfu2_to_f4(uint2 u) {
    __nv_bfloat162 a = *reinterpret_cast<__nv_bfloat162*>(&u.x);
    __nv_bfloat162 b = *reinterpret_cast<__nv_bfloat162*>(&u.y);
    float2 fa = __bfloat1622float2(a), fb = __bfloat1622float2(b);
    return make_float4(fa.x, fa.y, fb.x, fb.y);
}
static __device__ __forceinline__ void split_pk(float x, float y, uint32_t& hi, uint32_t& lo) {
    __nv_bfloat16 hx = __float2bfloat16(x);
    __nv_bfloat16 hy = __float2bfloat16(y);
    __nv_bfloat162 h2; h2.x = hx; h2.y = hy;
    hi = *reinterpret_cast<uint32_t*>(&h2);
    __nv_bfloat162 l2 = __floats2bfloat162_rn(x - __bfloat162float(hx),
                                              y - __bfloat162float(hy));
    lo = *reinterpret_cast<uint32_t*>(&l2);
}
static __device__ __forceinline__ void ldsm4(uint32_t r[4], uint32_t addr) {
    asm volatile("ldmatrix.sync.aligned.m8n8.x4.shared.b16 {%0,%1,%2,%3}, [%4];"
                 : "=r"(r[0]), "=r"(r[1]), "=r"(r[2]), "=r"(r[3]) : "r"(addr));
}
static __device__ __forceinline__ void ldsm4t(uint32_t r[4], uint32_t addr) {
    asm volatile("ldmatrix.sync.aligned.m8n8.x4.trans.shared.b16 {%0,%1,%2,%3}, [%4];"
                 : "=r"(r[0]), "=r"(r[1]), "=r"(r[2]), "=r"(r[3]) : "r"(addr));
}
static __device__ __forceinline__ void mma16816(float c[4], const uint32_t a[4],
                                                uint32_t b0, uint32_t b1) {
    asm volatile("mma.sync.aligned.m16n8k16.row.col.f32.bf16.bf16.f32 "
                 "{%0,%1,%2,%3}, {%4,%5,%6,%7}, {%8,%9}, {%0,%1,%2,%3};"
                 : "+f"(c[0]), "+f"(c[1]), "+f"(c[2]), "+f"(c[3])
                 : "r"(a[0]), "r"(a[1]), "r"(a[2]), "r"(a[3]), "r"(b0), "r"(b1));
}
static __device__ __forceinline__ void pdl_wait() {
#if __CUDA_ARCH__ >= 900
    cudaGridDependencySynchronize();
#endif
}
// L2 prefetch of a contiguous region (legal BEFORE pdl_wait for data written
// by kernels >=2 completed boundaries earlier; pure perf hint, no result change)
static __device__ __forceinline__ void l2_prefetch(const void* base, int bytes,
                                                   int t, int nthr) {
    const char* p = (const char*)base;
    for (int i = t * 128; i < bytes; i += nthr * 128)
        asm volatile("prefetch.global.L2 [%0];" :: "l"(p + i));
}

// -------- bf16 TC GEMM, K-split (grid.z=2), transposed epilogue + fused bias (z=0) --------
__global__ __launch_bounds__(256) void k_gemm_bf16T(const float* __restrict__ A,
                                                    const float* __restrict__ W,
                                                    const float* __restrict__ bias,
                                                    float* __restrict__ dstT,
                                                    int N, int nChunks) {
    __shared__ uint4 Asm[2][512];
    __shared__ uint4 Bsm[2][512];
    const int t = threadIdx.x;
    const int n0 = blockIdx.x * 64;
    const int kb = blockIdx.z * nChunks * 64;
    const int lane = t & 31, w = t >> 5;
    const int m0 = (w & 3) * 16;
    const int nw0 = (w >> 2) * 32;
    const uint32_t aBase = smem_u32(Asm);
    const uint32_t bBase = smem_u32(Bsm);
    dstT += (size_t)blockIdx.z * LOGZ;
    // prefetch first two weight tiles (W is a kernel input, predecessor-independent)
    {
        const float* w0 = W + (size_t)kb * N + n0;
        for (int r = t >> 2; r < 128; r += 64) {
            int cq = (t & 3) * 16;
            if (n0 + cq < N)
                asm volatile("prefetch.global.L2 [%0];"
                             :: "l"((const char*)(w0 + (size_t)r * N + cq)));
        }
    }
    pdl_wait();

    float acc[4][4];
    #pragma unroll
    for (int j = 0; j < 4; j++)
        #pragma unroll
        for (int r = 0; r < 4; r++) acc[j][r] = 0.f;

    float4 ra[2][2], rb[2][2];
    auto loadStage = [&](int k0) {
        #pragma unroll
        for (int it = 0; it < 2; it++) {
            int idx = t + 256 * it;
            int r = idx >> 3, c = idx & 7;
            const float* ap = A + r * Un + k0 + c * 8;
            ra[it][0] = *(const float4*)ap;
            ra[it][1] = *(const float4*)(ap + 4);
            int n = n0 + c * 8;
            const float* wp = W + (size_t)(k0 + r) * N + n;
            if (n + 7 < N) {
                rb[it][0] = __ldcs((const float4*)wp);
                rb[it][1] = __ldcs((const float4*)(wp + 4));
            } else {
                float v[8];
                #pragma unroll
                for (int j = 0; j < 8; j++) v[j] = (n + j < N) ? wp[j] : 0.f;
                rb[it][0] = make_float4(v[0], v[1], v[2], v[3]);
                rb[it][1] = make_float4(v[4], v[5], v[6], v[7]);
            }
        }
    };
    auto stsStage = [&](int buf) {
        #pragma unroll
        for (int it = 0; it < 2; it++) {
            int idx = t + 256 * it;
            int r = idx >> 3, c = idx & 7;
            int u = r * 8 + (c ^ (r & 7));
            Asm[buf][u] = make_uint4(pk2(ra[it][0].x, ra[it][0].y), pk2(ra[it][0].z, ra[it][0].w),
                                     pk2(ra[it][1].x, ra[it][1].y), pk2(ra[it][1].z, ra[it][1].w));
            Bsm[buf][u] = make_uint4(pk2(rb[it][0].x, rb[it][0].y), pk2(rb[it][0].z, rb[it][0].w),
                                     pk2(rb[it][1].x, rb[it][1].y), pk2(rb[it][1].z, rb[it][1].w));
        }
    };

    loadStage(kb);
    stsStage(0);
    __syncthreads();

    for (int ch = 0; ch < nChunks; ch++) {
        if (ch < nChunks - 1) loadStage(kb + (ch + 1) * 64);
        const int buf = ch & 1;
        const uint32_t aB = aBase + buf * 8192;
        const uint32_t bB = bBase + buf * 8192;
        #pragma unroll
        for (int ksi = 0; ksi < 4; ksi++) {
            const int ks = ksi * 16;
            uint32_t af[4], bf0[4], bf1[4];
            { int r = m0 + (lane & 15), c = (ks >> 3) + (lane >> 4);
              ldsm4(af, aB + (uint32_t)(r * 8 + (c ^ (r & 7))) * 16); }
            { int r = ks + (lane & 15), c = (nw0 >> 3) + (lane >> 4);
              ldsm4t(bf0, bB + (uint32_t)(r * 8 + (c ^ (r & 7))) * 16); }
            { int r = ks + (lane & 15), c = ((nw0 + 16) >> 3) + (lane >> 4);
              ldsm4t(bf1, bB + (uint32_t)(r * 8 + (c ^ (r & 7))) * 16); }
            mma16816(acc[0], af, bf0[0], bf0[1]);
            mma16816(acc[1], af, bf0[2], bf0[3]);
            mma16816(acc[2], af, bf1[0], bf1[1]);
            mma16816(acc[3], af, bf1[2], bf1[3]);
        }
        if (ch < nChunks - 1) stsStage(buf ^ 1);
        __syncthreads();
    }

    const bool addB = (blockIdx.z == 0);
    const int g = lane >> 2, tg = lane & 3;
    #pragma unroll
    for (int j = 0; j < 4; j++) {
        int ncol = n0 + nw0 + j * 8 + tg * 2;
        int m_lo = m0 + g, m_hi = m0 + g + 8;
        #pragma unroll
        for (int e = 0; e < 2; e++) {
            int n = ncol + e;
            if (n < N) {
                float bv = addB ? bias[n] : 0.f;
                int h = n & 15, s = n >> 4;
                dstT[(size_t)(m_lo * Hn + h) * SLP + s] = acc[j][e] + bv;
                dstT[(size_t)(m_hi * Hn + h) * SLP + s] = acc[j][2 + e] + bv;
            }
        }
    }
}

// -------- bf16x3 split GEMM for Wk (K-split x8) --------
__global__ __launch_bounds__(256) void k_gemm_x3(const float* __restrict__ A,
                                                 const float* __restrict__ W,
                                                 float* __restrict__ kpart) {
    __shared__ uint4 S4[4][512];
    const int t = threadIdx.x;
    const int n0 = blockIdx.x * 64;
    const int kb = blockIdx.z * 128;
    const int lane = t & 31, w = t >> 5;
    const int m0 = (w & 3) * 16;
    const int nw0 = (w >> 2) * 32;
    const uint32_t base = smem_u32(S4);
    // prefetch this CTA's full weight slice (W independent of predecessor)
    {
        const float* w0 = W + (size_t)kb * Un + n0;
        for (int r = t >> 1; r < 128; r += 128) {
            int cq = (t & 1) * 32;
            asm volatile("prefetch.global.L2 [%0];"
                         :: "l"((const char*)(w0 + (size_t)r * Un + cq)));
        }
    }
    pdl_wait();

    float acc[4][4];
    #pragma unroll
    for (int j = 0; j < 4; j++)
        #pragma unroll
        for (int r = 0; r < 4; r++) acc[j][r] = 0.f;

    #pragma unroll
    for (int ch = 0; ch < 2; ch++) {
        int k0 = kb + ch * 64;
        float4 ra[2][2], rb[2][2];
        #pragma unroll
        for (int it = 0; it < 2; it++) {
            int idx = t + 256 * it;
            int r = idx >> 3, c = idx & 7;
            const float* ap = A + r * Un + k0 + c * 8;
            ra[it][0] = *(const float4*)ap;
            ra[it][1] = *(const float4*)(ap + 4);
            const float* wp = W + (size_t)(k0 + r) * Un + n0 + c * 8;
            rb[it][0] = __ldcs((const float4*)wp);
            rb[it][1] = __ldcs((const float4*)(wp + 4));
        }
        __syncthreads();
        #pragma unroll
        for (int it = 0; it < 2; it++) {
            int idx = t + 256 * it;
            int r = idx >> 3, c = idx & 7;
            int u = r * 8 + (c ^ (r & 7));
            uint32_t h0,l0,h1,l1,h2,l2,h3,l3;
            split_pk(ra[it][0].x, ra[it][0].y, h0, l0);
            split_pk(ra[it][0].z, ra[it][0].w, h1, l1);
            split_pk(ra[it][1].x, ra[it][1].y, h2, l2);
            split_pk(ra[it][1].z, ra[it][1].w, h3, l3);
            S4[0][u] = make_uint4(h0, h1, h2, h3);
            S4[1][u] = make_uint4(l0, l1, l2, l3);
            split_pk(rb[it][0].x, rb[it][0].y, h0, l0);
            split_pk(rb[it][0].z, rb[it][0].w, h1, l1);
            split_pk(rb[it][1].x, rb[it][1].y, h2, l2);
            split_pk(rb[it][1].z, rb[it][1].w, h3, l3);
            S4[2][u] = make_uint4(h0, h1, h2, h3);
            S4[3][u] = make_uint4(l0, l1, l2, l3);
        }
        __syncthreads();
        #pragma unroll
        for (int ksi = 0; ksi < 4; ksi++) {
            const int ks = ksi * 16;
            uint32_t ah[4], al[4], bh0[4], bh1[4], bl0[4], bl1[4];
            int ra_ = m0 + (lane & 15), ca = (ks >> 3) + (lane >> 4);
            uint32_t aoff = (uint32_t)(ra_ * 8 + (ca ^ (ra_ & 7))) * 16;
            ldsm4(ah, base + aoff);
            ldsm4(al, base + 8192 + aoff);
            int rb_ = ks + (lane & 15);
            int cb0 = (nw0 >> 3) + (lane >> 4), cb1 = ((nw0 + 16) >> 3) + (lane >> 4);
            uint32_t b0off = (uint32_t)(rb_ * 8 + (cb0 ^ (rb_ & 7))) * 16;
            uint32_t b1off = (uint32_t)(rb_ * 8 + (cb1 ^ (rb_ & 7))) * 16;
            ldsm4t(bh0, base + 16384 + b0off);
            ldsm4t(bh1, base + 16384 + b1off);
            ldsm4t(bl0, base + 24576 + b0off);
            ldsm4t(bl1, base + 24576 + b1off);
            mma16816(acc[0], ah, bh0[0], bh0[1]);
            mma16816(acc[0], ah, bl0[0], bl0[1]);
            mma16816(acc[0], al, bh0[0], bh0[1]);
            mma16816(acc[1], ah, bh0[2], bh0[3]);
            mma16816(acc[1], ah, bl0[2], bl0[3]);
            mma16816(acc[1], al, bh0[2], bh0[3]);
            mma16816(acc[2], ah, bh1[0], bh1[1]);
            mma16816(acc[2], ah, bl1[0], bl1[1]);
            mma16816(acc[2], al, bh1[0], bh1[1]);
            mma16816(acc[3], ah, bh1[2], bh1[3]);
            mma16816(acc[3], ah, bl1[2], bl1[3]);
            mma16816(acc[3], al, bh1[2], bh1[3]);
        }
    }
    size_t zo = (size_t)blockIdx.z * Bn * Un;
    const int g = lane >> 2, tg = lane & 3;
    #pragma unroll
    for (int j = 0; j < 4; j++) {
        int ncol = n0 + nw0 + j * 8 + tg * 2;
        int m_lo = m0 + g, m_hi = m0 + g + 8;
        *(float2*)&kpart[zo + (size_t)m_lo * Un + ncol] = make_float2(acc[j][0], acc[j][1]);
        *(float2*)&kpart[zo + (size_t)m_hi * Un + ncol] = make_float2(acc[j][2], acc[j][3]);
    }
}

// -------- rw softmax: 2 warps per (b,h) row, 4 rows per CTA --------
__global__ __launch_bounds__(256) void k_softmax513(const float* __restrict__ logitT,
                                                    float* __restrict__ probT,
                                                    const float* __restrict__ A,
                                                    float* __restrict__ cArr, int l) {
    __shared__ float smx[4][2], ssum[4][2], sdot[4][2];
    constexpr int IT = 9;
    int t = threadIdx.x, w = t >> 5, lane = t & 31;
    int r = w >> 1, half = w & 1;
    int gw = blockIdx.x * 4 + r;
    pdl_wait();
    const float* basep = logitT + (size_t)gw * SLP;
    float vals[IT];
    float mx = -1e30f;
    #pragma unroll
    for (int i = 0; i < IT; i++) {
        int s = half * 256 + i * 32 + lane;
        bool ok = half ? (s < NSLOT) : (i < 8);
        float v = ok ? (basep[s] + basep[LOGZ + s]) : -1e30f;
        vals[i] = v;
        mx = fmaxf(mx, v);
    }
    #pragma unroll
    for (int o = 16; o; o >>= 1) mx = fmaxf(mx, __shfl_xor_sync(0xffffffffu, mx, o));
    if (lane == 0) smx[r][half] = mx;
    __syncthreads();
    mx = fmaxf(smx[r][0], smx[r][1]);
    float sum = 0.f;
    #pragma unroll
    for (int i = 0; i < IT; i++) {
        int s = half * 256 + i * 32 + lane;
        bool ok = half ? (s < NSLOT) : (i < 8);
        float e = ok ? __expf(vals[i] - mx) : 0.f;
        vals[i] = e;
        sum += e;
    }
    #pragma unroll
    for (int o = 16; o; o >>= 1) sum += __shfl_xor_sync(0xffffffffu, sum, o);
    if (lane == 0) ssum[r][half] = sum;
    __syncthreads();
    float inv = 1.f / (ssum[r][0] + ssum[r][1]);
    float* dst = probT + (size_t)gw * SLP;
    #pragma unroll
    for (int i = 0; i < IT; i++) {
        int s = half * 256 + i * 32 + lane;
        bool ok = half ? (s < NSLOT) : (i < 8);
        if (ok) dst[s] = vals[i] * inv;
    }
    float dot = 0.f;
    const float* ap = A + (size_t)gw * BHR;
    #pragma unroll
    for (int i = 0; i < 8; i++) {
        int m = half * 256 + i * 32 + lane;
        float pv = vals[i] * inv;
        dot += (l > 0) ? pv * ap[m] : pv;
    }
    #pragma unroll
    for (int o = 16; o; o >>= 1) dot += __shfl_xor_sync(0xffffffffu, dot, o);
    if (lane == 0) sdot[r][half] = dot;
    __syncthreads();
    if (half == 0 && lane == 0)
        cArr[gw] = (sdot[r][0] + sdot[r][1]) * (1.f / 512.f);
}

// -------- fused ww-softmax (2 halves) + coefficient recurrence --------
__global__ __launch_bounds__(128) void k_smcoef(const float* __restrict__ wlogT,
                                                float* __restrict__ A,
                                                float* __restrict__ wA,
                                                float* __restrict__ B,
                                                float* __restrict__ sB, int l) {
    __shared__ float redm[4], reds[4], wred[4][4];
    int row = blockIdx.x;
    int t = threadIdx.x;
    int w = t >> 5, lane = t & 31;
    pdl_wait();

    float4 lg  = ((const float4*)(wlogT + (size_t)row*SLP))[t];
    float4 lg1 = ((const float4*)(wlogT + LOGZ + (size_t)row*SLP))[t];
    lg.x += lg1.x; lg.y += lg1.y; lg.z += lg1.z; lg.w += lg1.w;
    float mx = fmaxf(fmaxf(lg.x, lg.y), fmaxf(lg.z, lg.w));
    #pragma unroll
    for (int o = 16; o; o >>= 1) mx = fmaxf(mx, __shfl_xor_sync(0xffffffffu, mx, o));
    if (lane == 0) redm[w] = mx;
    __syncthreads();
    mx = fmaxf(fmaxf(redm[0], redm[1]), fmaxf(redm[2], redm[3]));
    float4 e = make_float4(__expf(lg.x - mx), __expf(lg.y - mx),
                           __expf(lg.z - mx), __expf(lg.w - mx));
    float s = e.x + e.y + e.z + e.w;
    #pragma unroll
    for (int o = 16; o; o >>= 1) s += __shfl_xor_sync(0xffffffffu, s, o);
    if (lane == 0) reds[w] = s;
    __syncthreads();
    float inv = 1.f / (reds[0] + reds[1] + reds[2] + reds[3]);
    float4 ww = make_float4(e.x * inv, e.y * inv, e.z * inv, e.w * inv);

    float4 om = make_float4(1.f-ww.x, 1.f-ww.y, 1.f-ww.z, 1.f-ww.w);
    float4 aold;
    if (l == 0) aold = make_float4(1.f, 1.f, 1.f, 1.f);
    else        aold = ((const float4*)(A + (size_t)row*BHR))[t];
    if (l < 3) {
        ((float4*)(wA + (size_t)row*BHR))[t] =
            make_float4(aold.x*ww.x, aold.y*ww.y, aold.z*ww.z, aold.w*ww.w);
    }
    ((float4*)(A + (size_t)row*BHR))[t] =
        make_float4(aold.x*om.x, aold.y*om.y, aold.z*om.z, aold.w*om.w);
    float sums[4] = {0.f, 0.f, 0.f, 0.f};
    for (int j = 0; j < l; j++) {
        float4* bp = (float4*)(B + (size_t)j*BSTR + (size_t)row*BHR);
        float4 bv = bp[t];
        bv.x *= om.x; bv.y *= om.y; bv.z *= om.z; bv.w *= om.w;
        bp[t] = bv;
        sums[j] = bv.x + bv.y + bv.z + bv.w;
    }
    ((float4*)(B + (size_t)l*BSTR + (size_t)row*BHR))[t] = ww;
    sums[l] = ww.x + ww.y + ww.z + ww.w;
    for (int j = 0; j <= l; j++) {
        float ss = sums[j];
        #pragma unroll
        for (int o = 16; o; o >>= 1) ss += __shfl_xor_sync(0xffffffffu, ss, o);
        if (lane == 0) wred[w][j] = ss;
    }
    __syncthreads();
    if (t == 0) {
        for (int j = 0; j <= l; j++)
            sB[j*Bn*Hn + row] = wred[0][j] + wred[1][j] + wred[2][j] + wred[3][j];
    }
}

// -------- initial: fp32 slot-sum partials + bf16 conversion --------
__global__ __launch_bounds__(256) void k_convsum(const float* __restrict__ mem,
                                                 __nv_bfloat16* __restrict__ memh,
                                                 float* __restrict__ part) {
    int b = blockIdx.x, c = blockIdx.y, t = threadIdx.x;
    pdl_wait();
    size_t base = (size_t)(b*Mn + c*MCH)*U4 + t;
    const float4* m4 = (const float4*)mem + base;
    uint2* o2 = (uint2*)memh + base;
    float ax=0.f, ay=0.f, az=0.f, aw=0.f;
    #pragma unroll 8
    for (int i = 0; i < MCH; i++) {
        float4 v = __ldcs(m4 + (size_t)i*U4);
        ax += v.x; ay += v.y; az += v.z; aw += v.w;
        __nv_bfloat162 p0 = __floats2bfloat162_rn(v.x, v.y);
        __nv_bfloat162 p1 = __floats2bfloat162_rn(v.z, v.w);
        o2[(size_t)i*U4] = make_uint2(*reinterpret_cast<uint32_t*>(&p0),
                                      *reinterpret_cast<uint32_t*>(&p1));
    }
    ((float4*)part)[(b*NCH + c)*U4 + t] = make_float4(ax, ay, az, aw);
}

// -------- mean-subtracted weighted pass over bf16 mem (L2-prefetch pre-wait) --------
__global__ __launch_bounds__(256) void k_wpass(const __nv_bfloat16* __restrict__ memh,
                                               const float* __restrict__ rwT,
                                               const float* __restrict__ A,
                                               const float* __restrict__ cArr,
                                               float* __restrict__ part, int l) {
    __shared__ float ws[MCH][17];
    int b = blockIdx.x, c = blockIdx.y, t = threadIdx.x;
    // warm L2 with this CTA's memh tile while the predecessor finishes
    l2_prefetch(memh + (size_t)(b*Mn + c*MCH)*Un, MCH*Un*2, t, 256);
    pdl_wait();
    #pragma unroll
    for (int it = 0; it < 2; it++) {
        int idx = t + 256 * it;
        int hh = idx >> 5, s = idx & 31;
        int m = c * MCH + s;
        float v = rwT[(size_t)(b*Hn + hh)*SLP + m];
        if (l > 0) v *= A[(size_t)(b*Hn + hh)*BHR + m];
        ws[s][hh] = v - cArr[b*Hn + hh];
    }
    __syncthreads();
    int h = t >> 4;
    const uint2* m2 = (const uint2*)memh + (size_t)(b*Mn + c*MCH)*U4 + t;
    float ax=0.f, ay=0.f, az=0.f, aw=0.f;
    #pragma unroll 8
    for (int i = 0; i < MCH; i++) {
        float4 v = bfu2_to_f4(m2[(size_t)i*U4]);
        float wv = ws[i][h];
        ax += wv*v.x; ay += wv*v.y; az += wv*v.z; aw += wv*v.w;
    }
    ((float4*)part)[(b*NCH + c)*U4 + t] = make_float4(ax, ay, az, aw);
}

// -------- T pass over bf16 mem (L2-prefetch pre-wait) --------
__global__ __launch_bounds__(256) void k_tpass(const __nv_bfloat16* __restrict__ memh,
                                               const float* __restrict__ wA,
                                               float* __restrict__ part) {
    __shared__ float ws[MCH][17];
    int b = blockIdx.x, c = blockIdx.y, t = threadIdx.x;
    l2_prefetch(memh + (size_t)(b*Mn + c*MCH)*Un, MCH*Un*2, t, 256);
    pdl_wait();
    #pragma unroll
    for (int it = 0; it < 2; it++) {
        int idx = t + 256 * it;
        int hh = idx >> 5, s = idx & 31;
        ws[s][hh] = wA[(size_t)(b*Hn + hh)*BHR + c*MCH + s];
    }
    __syncthreads();
    int h = t >> 4;
    const uint2* m2 = (const uint2*)memh + (size_t)(b*Mn + c*MCH)*U4 + t;
    float ax=0.f, ay=0.f, az=0.f, aw=0.f;
    #pragma unroll 8
    for (int i = 0; i < MCH; i++) {
        float4 v = bfu2_to_f4(m2[(size_t)i*U4]);
        float wv = ws[i][h];
        ax += wv*v.x; ay += wv*v.y; az += wv*v.z; aw += wv*v.w;
    }
    ((float4*)part)[(b*NCH + c)*U4 + t] = make_float4(ax, ay, az, aw);
}

// -------- S update + memstate (captures fp32 SlotSum at l=0) --------
__global__ __launch_bounds__(256) void k_state(const float* __restrict__ part,
                                               float* __restrict__ S,
                                               float* __restrict__ slot,
                                               const float* __restrict__ nv,
                                               const float* __restrict__ sB,
                                               const float* __restrict__ prev,
                                               float* __restrict__ state, int l) {
    int b = blockIdx.x, t = threadIdx.x, h = t >> 4;
    pdl_wait();
    float4 p = make_float4(0.f, 0.f, 0.f, 0.f);
    #pragma unroll
    for (int c = 0; c < NCH; c++) {
        float4 v = ((const float4*)part)[(b*NCH + c)*U4 + t];
        p.x += v.x; p.y += v.y; p.z += v.z; p.w += v.w;
    }
    float4 s;
    if (l == 0) {
        s = p;
        ((float4*)slot)[b*U4 + t] = p;
    } else {
        s = ((const float4*)S)[b*U4 + t];
        s.x -= p.x; s.y -= p.y; s.z -= p.z; s.w -= p.w;
    }
    ((float4*)S)[b*U4 + t] = s;
    float4 a = ((const float4*)prev)[b*U4 + t];
    a.x += s.x; a.y += s.y; a.z += s.z; a.w += s.w;
    for (int j = 0; j < l; j++) {
        float cf = sB[j*Bn*Hn + b*Hn + h];
        float4 n = ((const float4*)nv)[j*NV4 + b*U4 + t];
        a.x += cf*n.x; a.y += cf*n.y; a.z += cf*n.z; a.w += cf*n.w;
    }
    const float inv = 1.f / 513.f;
    a.x *= inv; a.y *= inv; a.z *= inv; a.w *= inv;
    ((float4*)state)[b*U4 + t] = a;
}

// -------- read finalize --------
__global__ __launch_bounds__(256) void k_readfin(const float* __restrict__ part,
                                                 const float* __restrict__ rwT,
                                                 const float* __restrict__ B,
                                                 const float* __restrict__ nv,
                                                 const float* __restrict__ prev,
                                                 const float* __restrict__ slot,
                                                 const float* __restrict__ cArr,
                                                 float* __restrict__ readv, int l) {
    __shared__ float sRB[3][16];
    int b = blockIdx.x, t = threadIdx.x;
    int w = t >> 5, lane = t & 31;
    pdl_wait();
    for (int task = w; task < l * 16; task += 8) {
        int j = task >> 4, h = task & 15;
        const float* rwp = rwT + (size_t)(b*Hn + h)*SLP;
        const float* bp  = B + (size_t)j*BSTR + (size_t)(b*Hn + h)*BHR;
        float s = 0.f;
        #pragma unroll
        for (int i = 0; i < 16; i++) s += rwp[lane + 32*i] * bp[lane + 32*i];
        #pragma unroll
        for (int o = 16; o; o >>= 1) s += __shfl_xor_sync(0xffffffffu, s, o);
        if (lane == 0) sRB[j][h] = s;
    }
    __syncthreads();
    int h = t >> 4;
    float cc = cArr[b*Hn + h];
    float4 sl = ((const float4*)slot)[b*U4 + t];
    float4 a = make_float4(cc*sl.x, cc*sl.y, cc*sl.z, cc*sl.w);
    #pragma unroll
    for (int c = 0; c < NCH; c++) {
        float4 v = ((const float4*)part)[(b*NCH + c)*U4 + t];
        a.x += v.x; a.y += v.y; a.z += v.z; a.w += v.w;
    }
    for (int j = 0; j < l; j++) {
        float cf = sRB[j][h];
        float4 n = ((const float4*)nv)[j*NV4 + b*U4 + t];
        a.x += cf*n.x; a.y += cf*n.y; a.z += cf*n.z; a.w += cf*n.w;
    }
    float wl = rwT[(size_t)(b*Hn + h)*SLP + Mn];
    float4 pv = ((const float4*)prev)[b*U4 + t];
    a.x += wl*pv.x; a.y += wl*pv.y; a.z += wl*pv.z; a.w += wl*pv.w;
    ((float4*)readv)[b*U4 + t] = a;
}

// -------- combine K-split (x8) + bias + relu --------
__global__ __launch_bounds__(256) void k_wk_reduce(const float* __restrict__ part,
                                                   const float* __restrict__ bk,
                                                   float* __restrict__ nvout,
                                                   float* __restrict__ out2) {
    int b = blockIdx.x, t = threadIdx.x;
    pdl_wait();
    float4 a = ((const float4*)bk)[t];
    #pragma unroll
    for (int z = 0; z < KZ; z++) {
        float4 v = ((const float4*)part)[((size_t)z*Bn + b)*U4 + t];
        a.x += v.x; a.y += v.y; a.z += v.z; a.w += v.w;
    }
    a.x = fmaxf(a.x, 0.f); a.y = fmaxf(a.y, 0.f);
    a.z = fmaxf(a.z, 0.f); a.w = fmaxf(a.w, 0.f);
    ((float4*)nvout)[b*U4 + t] = a;
    if (out2) ((float4*)out2)[b*U4 + t] = a;
}

// -------- final reconstruction (fp32 mem0, L2-prefetch pre-wait) --------
__global__ __launch_bounds__(256) void k_recon(const float* __restrict__ mem,
                                               const float* __restrict__ A,
                                               const float* __restrict__ B,
                                               const float* __restrict__ nv,
                                               float* __restrict__ outm) {
    __shared__ float sA[MCH][17];
    __shared__ float sBs[4][MCH][17];
    int b = blockIdx.x, c = blockIdx.y, t = threadIdx.x;
    l2_prefetch(mem + (size_t)(b*Mn + c*MCH)*Un, MCH*Un*4, t, 256);
    pdl_wait();
    #pragma unroll
    for (int it = 0; it < 2; it++) {
        int idx = t + 256 * it;
        int hh = idx >> 5, s = idx & 31;
        size_t ro = (size_t)(b*Hn + hh)*BHR + c*MCH + s;
        sA[s][hh] = A[ro];
        #pragma unroll
        for (int j = 0; j < 4; j++) sBs[j][s][hh] = B[(size_t)j*BSTR + ro];
    }
    __syncthreads();
    int h = t >> 4;
    float4 n0 = ((const float4*)nv)[0*NV4 + b*U4 + t];
    float4 n1 = ((const float4*)nv)[1*NV4 + b*U4 + t];
    float4 n2 = ((const float4*)nv)[2*NV4 + b*U4 + t];
    float4 n3 = ((const float4*)nv)[3*NV4 + b*U4 + t];
    size_t basei = (size_t)(b*Mn + c*MCH)*U4 + t;
    const float4* mi = (const float4*)mem;
    float4* mo = (float4*)outm;
    #pragma unroll 4
    for (int i = 0; i < MCH; i++) {
        float4 v = __ldcs(mi + basei + (size_t)i*U4);
        float a  = sA[i][h];
        float b0 = sBs[0][i][h], b1 = sBs[1][i][h], b2 = sBs[2][i][h], b3 = sBs[3][i][h];
        float4 r;
        r.x = a*v.x + b0*n0.x + b1*n1.x + b2*n2.x + b3*n3.x;
        r.y = a*v.y + b0*n0.y + b1*n1.y + b2*n2.y + b3*n3.y;
        r.z = a*v.z + b0*n0.z + b1*n1.z + b2*n2.z + b3*n3.z;
        r.w = a*v.w + b0*n0.w + b1*n1.w + b2*n2.w + b3*n3.w;
        mo[basei + (size_t)i*U4] = r;
    }
}

// -------- host: PDL launch helper --------
template <typename F, typename... Args>
static inline void pdl(F kern, dim3 grid, dim3 blk, Args... args) {
    cudaLaunchConfig_t cfg = {};
    cfg.gridDim = grid;
    cfg.blockDim = blk;
    cudaLaunchAttribute attr = {};
    attr.id = cudaLaunchAttributeProgrammaticStreamSerialization;
    attr.val.programmaticStreamSerializationAllowed = 1;
    cfg.attrs = &attr;
    cfg.numAttrs = 1;
    cudaLaunchKernelEx(&cfg, kern, args...);
}

// -------- host orchestration --------
extern "C" void kernel_launch(void* const* d_in, const int* in_sizes, int n_in,
                              void* d_out, int out_size) {
    const float* x      = (const float*)d_in[0];
    const float* mem0   = (const float*)d_in[1];
    const float* Wr     = (const float*)d_in[2];
    const float* br     = (const float*)d_in[3];
    const float* Ww     = (const float*)d_in[4];
    const float* bw     = (const float*)d_in[5];
    const float* Wk     = (const float*)d_in[6];
    const float* bk     = (const float*)d_in[7];
    float* outp    = (float*)d_out;
    float* out_mem = outp + Bn*Un;

    float *p_part, *p_S, *p_slot, *p_state, *p_rlogT, *p_rwT, *p_wlogT, *p_c;
    float *p_read, *p_nv, *p_kpart, *p_A, *p_wA, *p_B, *p_sB;
    __nv_bfloat16* p_memh;
    cudaGetSymbolAddress((void**)&p_memh,  g_memh);
    cudaGetSymbolAddress((void**)&p_part,  g_part);
    cudaGetSymbolAddress((void**)&p_S,     g_S);
    cudaGetSymbolAddress((void**)&p_slot,  g_slot);
    cudaGetSymbolAddress((void**)&p_state, g_state);
    cudaGetSymbolAddress((void**)&p_rlogT, g_rlogT);
    cudaGetSymbolAddress((void**)&p_rwT,   g_rwT);
    cudaGetSymbolAddress((void**)&p_wlogT, g_wlogT);
    cudaGetSymbolAddress((void**)&p_c,     g_cmean);
    cudaGetSymbolAddress((void**)&p_read,  g_read);
    cudaGetSymbolAddress((void**)&p_nv,    g_nv);
    cudaGetSymbolAddress((void**)&p_kpart, g_kpart);
    cudaGetSymbolAddress((void**)&p_A,     g_A);
    cudaGetSymbolAddress((void**)&p_wA,    g_wA);
    cudaGetSymbolAddress((void**)&p_B,     g_B);
    cudaGetSymbolAddress((void**)&p_sB,    g_sB);

    dim3 blk(256);
    pdl(k_convsum, dim3(Bn, NCH), blk,
        mem0, (__nv_bfloat16*)p_memh, (float*)p_part);

    const float* prev = x;
    for (int l = 0; l < Dn; l++) {
        float* nv_l = p_nv + (size_t)l * Bn * Un;

        pdl(k_state, dim3(Bn), blk,
            (const float*)p_part, p_S, p_slot, (const float*)p_nv,
            (const float*)p_sB, prev, p_state, l);
        pdl(k_gemm_bf16T, dim3(129, 1, 2), blk,
            (const float*)p_state, Wr + (size_t)l*Un*NRr, br + (size_t)l*NRr,
            p_rlogT, (int)NRr, 8);
        pdl(k_softmax513, dim3(256), dim3(256),
            (const float*)p_rlogT, p_rwT, (const float*)p_A, p_c, l);

        pdl(k_wpass, dim3(Bn, NCH), blk,
            (const __nv_bfloat16*)p_memh, (const float*)p_rwT, (const float*)p_A,
            (const float*)p_c, p_part, l);
        pdl(k_readfin, dim3(Bn), blk,
            (const float*)p_part, (const float*)p_rwT, (const float*)p_B,
            (const float*)p_nv, prev, (const float*)p_slot, (const float*)p_c,
            p_read, l);

        pdl(k_gemm_x3, dim3(16, 1, KZ), blk,
            (const float*)p_read, Wk + (size_t)l*Un*Un, p_kpart);
        pdl(k_wk_reduce, dim3(Bn), blk,
            (const float*)p_kpart, bk + (size_t)l*Un, nv_l,
            (l == Dn-1) ? outp : (float*)nullptr);

        pdl(k_gemm_bf16T, dim3(128, 1, 2), blk,
            (const float*)nv_l, Ww + (size_t)l*Un*NWw, bw + (size_t)l*NWw,
            p_wlogT, (int)NWw, 8);
        pdl(k_smcoef, dim3(Bn*Hn), dim3(128),
            (const float*)p_wlogT, p_A, p_wA, p_B, p_sB, l);

        if (l < Dn - 1)
            pdl(k_tpass, dim3(Bn, NCH), blk,
                (const __nv_bfloat16*)p_memh, (const float*)p_wA, p_part);

        prev = nv_l;
    }

    pdl(k_recon, dim3(Bn, NCH), blk,
        mem0, (const float*)p_A, (const float*)p_B, (const float*)p_nv, out_mem);
}

// round 15
// speedup vs baseline: 1.0460x; 1.0460x over previous
#include <cuda_runtime.h>
#include <cuda_bf16.h>
#include <math.h>
#include <stdint.h>

// Problem constants
#define Bn 64
#define Un 1024
#define Hn 16
#define Mn 512
#define Dn 4
#define NSLOT 513
#define NRr 8208
#define NWw 8192
#define U4 256
#define MCH 32
#define NCH 16
#define SLP 520
#define BHR 512
#define BSTR 524288
#define NV4 16384
#define LOGZ (Bn*Hn*SLP)
#define KZ 8                 // K-split factor for Wk GEMM

// -------- scratch --------
__device__ __nv_bfloat16 g_memh[Bn*Mn*Un];
__device__ float g_part [Bn*NCH*Un];
__device__ float g_S    [Bn*Un];
__device__ float g_slot [Bn*Un];
__device__ float g_state[Bn*Un];
__device__ float g_rlogT[2*LOGZ];
__device__ float g_rwT  [Bn*Hn*SLP];
__device__ float g_wlogT[2*LOGZ];
__device__ float g_cmean[Bn*Hn];
__device__ float g_read [Bn*Un];
__device__ float g_nv   [4*Bn*Un];
__device__ float g_kpart[KZ*Bn*Un];
__device__ float g_A    [Bn*Hn*BHR];
__device__ float g_wA   [Bn*Hn*BHR];
__device__ float g_B    [4*Bn*Hn*BHR];
__device__ float g_sB   [4*Bn*Hn];

// -------- helpers --------
static __device__ __forceinline__ uint32_t smem_u32(const void* p) {
    return (uint32_t)__cvta_generic_to_shared(p);
}
static __device__ __forceinline__ uint32_t pk2(float a, float b) {
    __nv_bfloat162 t = __floats2bfloat162_rn(a, b);
    return *reinterpret_cast<uint32_t*>(&t);
}
static __device__ __forceinline__ float4 bfu2_to_f4(uint2 u) {
    __nv_bfloat162 a = *reinterpret_cast<__nv_bfloat162*>(&u.x);
    __nv_bfloat162 b = *reinterpret_cast<__nv_bfloat162*>(&u.y);
    float2 fa = __bfloat1622float2(a), fb = __bfloat1622float2(b);
    return make_float4(fa.x, fa.y, fb.x, fb.y);
}
static __device__ __forceinline__ void split_pk(float x, float y, uint32_t& hi, uint32_t& lo) {
    __nv_bfloat16 hx = __float2bfloat16(x);
    __nv_bfloat16 hy = __float2bfloat16(y);
    __nv_bfloat162 h2; h2.x = hx; h2.y = hy;
    hi = *reinterpret_cast<uint32_t*>(&h2);
    __nv_bfloat162 l2 = __floats2bfloat162_rn(x - __bfloat162float(hx),
                                              y - __bfloat162float(hy));
    lo = *reinterpret_cast<uint32_t*>(&l2);
}
static __device__ __forceinline__ void ldsm4(uint32_t r[4], uint32_t addr) {
    asm volatile("ldmatrix.sync.aligned.m8n8.x4.shared.b16 {%0,%1,%2,%3}, [%4];"
                 : "=r"(r[0]), "=r"(r[1]), "=r"(r[2]), "=r"(r[3]) : "r"(addr));
}
static __device__ __forceinline__ void ldsm4t(uint32_t r[4], uint32_t addr) {
    asm volatile("ldmatrix.sync.aligned.m8n8.x4.trans.shared.b16 {%0,%1,%2,%3}, [%4];"
                 : "=r"(r[0]), "=r"(r[1]), "=r"(r[2]), "=r"(r[3]) : "r"(addr));
}
static __device__ __forceinline__ void mma16816(float c[4], const uint32_t a[4],
                                                uint32_t b0, uint32_t b1) {
    asm volatile("mma.sync.aligned.m16n8k16.row.col.f32.bf16.bf16.f32 "
                 "{%0,%1,%2,%3}, {%4,%5,%6,%7}, {%8,%9}, {%0,%1,%2,%3};"
                 : "+f"(c[0]), "+f"(c[1]), "+f"(c[2]), "+f"(c[3])
                 : "r"(a[0]), "r"(a[1]), "r"(a[2]), "r"(a[3]), "r"(b0), "r"(b1));
}
static __device__ __forceinline__ void pdl_wait() {
#if __CUDA_ARCH__ >= 900
    cudaGridDependencySynchronize();
#endif
}

// -------- bf16 TC GEMM, K-split (grid.z=2), transposed epilogue + fused bias (z=0) --------
__global__ __launch_bounds__(256) void k_gemm_bf16T(const float* __restrict__ A,
                                                    const float* __restrict__ W,
                                                    const float* __restrict__ bias,
                                                    float* __restrict__ dstT,
                                                    int N, int nChunks) {
    __shared__ uint4 Asm[2][512];
    __shared__ uint4 Bsm[2][512];
    const int t = threadIdx.x;
    const int n0 = blockIdx.x * 64;
    const int kb = blockIdx.z * nChunks * 64;
    const int lane = t & 31, w = t >> 5;
    const int m0 = (w & 3) * 16;
    const int nw0 = (w >> 2) * 32;
    const uint32_t aBase = smem_u32(Asm);
    const uint32_t bBase = smem_u32(Bsm);
    dstT += (size_t)blockIdx.z * LOGZ;
    pdl_wait();

    float acc[4][4];
    #pragma unroll
    for (int j = 0; j < 4; j++)
        #pragma unroll
        for (int r = 0; r < 4; r++) acc[j][r] = 0.f;

    float4 ra[2][2], rb[2][2];
    auto loadStage = [&](int k0) {
        #pragma unroll
        for (int it = 0; it < 2; it++) {
            int idx = t + 256 * it;
            int r = idx >> 3, c = idx & 7;
            const float* ap = A + r * Un + k0 + c * 8;
            ra[it][0] = *(const float4*)ap;
            ra[it][1] = *(const float4*)(ap + 4);
            int n = n0 + c * 8;
            const float* wp = W + (size_t)(k0 + r) * N + n;
            if (n + 7 < N) {
                rb[it][0] = __ldcs((const float4*)wp);
                rb[it][1] = __ldcs((const float4*)(wp + 4));
            } else {
                float v[8];
                #pragma unroll
                for (int j = 0; j < 8; j++) v[j] = (n + j < N) ? wp[j] : 0.f;
                rb[it][0] = make_float4(v[0], v[1], v[2], v[3]);
                rb[it][1] = make_float4(v[4], v[5], v[6], v[7]);
            }
        }
    };
    auto stsStage = [&](int buf) {
        #pragma unroll
        for (int it = 0; it < 2; it++) {
            int idx = t + 256 * it;
            int r = idx >> 3, c = idx & 7;
            int u = r * 8 + (c ^ (r & 7));
            Asm[buf][u] = make_uint4(pk2(ra[it][0].x, ra[it][0].y), pk2(ra[it][0].z, ra[it][0].w),
                                     pk2(ra[it][1].x, ra[it][1].y), pk2(ra[it][1].z, ra[it][1].w));
            Bsm[buf][u] = make_uint4(pk2(rb[it][0].x, rb[it][0].y), pk2(rb[it][0].z, rb[it][0].w),
                                     pk2(rb[it][1].x, rb[it][1].y), pk2(rb[it][1].z, rb[it][1].w));
        }
    };

    loadStage(kb);
    stsStage(0);
    __syncthreads();

    for (int ch = 0; ch < nChunks; ch++) {
        if (ch < nChunks - 1) loadStage(kb + (ch + 1) * 64);
        const int buf = ch & 1;
        const uint32_t aB = aBase + buf * 8192;
        const uint32_t bB = bBase + buf * 8192;
        #pragma unroll
        for (int ksi = 0; ksi < 4; ksi++) {
            const int ks = ksi * 16;
            uint32_t af[4], bf0[4], bf1[4];
            { int r = m0 + (lane & 15), c = (ks >> 3) + (lane >> 4);
              ldsm4(af, aB + (uint32_t)(r * 8 + (c ^ (r & 7))) * 16); }
            { int r = ks + (lane & 15), c = (nw0 >> 3) + (lane >> 4);
              ldsm4t(bf0, bB + (uint32_t)(r * 8 + (c ^ (r & 7))) * 16); }
            { int r = ks + (lane & 15), c = ((nw0 + 16) >> 3) + (lane >> 4);
              ldsm4t(bf1, bB + (uint32_t)(r * 8 + (c ^ (r & 7))) * 16); }
            mma16816(acc[0], af, bf0[0], bf0[1]);
            mma16816(acc[1], af, bf0[2], bf0[3]);
            mma16816(acc[2], af, bf1[0], bf1[1]);
            mma16816(acc[3], af, bf1[2], bf1[3]);
        }
        if (ch < nChunks - 1) stsStage(buf ^ 1);
        __syncthreads();
    }

    const bool addB = (blockIdx.z == 0);
    const int g = lane >> 2, tg = lane & 3;
    #pragma unroll
    for (int j = 0; j < 4; j++) {
        int ncol = n0 + nw0 + j * 8 + tg * 2;
        int m_lo = m0 + g, m_hi = m0 + g + 8;
        #pragma unroll
        for (int e = 0; e < 2; e++) {
            int n = ncol + e;
            if (n < N) {
                float bv = addB ? bias[n] : 0.f;
                int h = n & 15, s = n >> 4;
                dstT[(size_t)(m_lo * Hn + h) * SLP + s] = acc[j][e] + bv;
                dstT[(size_t)(m_hi * Hn + h) * SLP + s] = acc[j][2 + e] + bv;
            }
        }
    }
}

// -------- bf16x3 split GEMM for Wk (K-split x8) --------
__global__ __launch_bounds__(256) void k_gemm_x3(const float* __restrict__ A,
                                                 const float* __restrict__ W,
                                                 float* __restrict__ kpart) {
    __shared__ uint4 S4[4][512];
    const int t = threadIdx.x;
    const int n0 = blockIdx.x * 64;
    const int kb = blockIdx.z * 128;
    const int lane = t & 31, w = t >> 5;
    const int m0 = (w & 3) * 16;
    const int nw0 = (w >> 2) * 32;
    const uint32_t base = smem_u32(S4);
    pdl_wait();

    float acc[4][4];
    #pragma unroll
    for (int j = 0; j < 4; j++)
        #pragma unroll
        for (int r = 0; r < 4; r++) acc[j][r] = 0.f;

    #pragma unroll
    for (int ch = 0; ch < 2; ch++) {
        int k0 = kb + ch * 64;
        float4 ra[2][2], rb[2][2];
        #pragma unroll
        for (int it = 0; it < 2; it++) {
            int idx = t + 256 * it;
            int r = idx >> 3, c = idx & 7;
            const float* ap = A + r * Un + k0 + c * 8;
            ra[it][0] = *(const float4*)ap;
            ra[it][1] = *(const float4*)(ap + 4);
            const float* wp = W + (size_t)(k0 + r) * Un + n0 + c * 8;
            rb[it][0] = __ldcs((const float4*)wp);
            rb[it][1] = __ldcs((const float4*)(wp + 4));
        }
        __syncthreads();
        #pragma unroll
        for (int it = 0; it < 2; it++) {
            int idx = t + 256 * it;
            int r = idx >> 3, c = idx & 7;
            int u = r * 8 + (c ^ (r & 7));
            uint32_t h0,l0,h1,l1,h2,l2,h3,l3;
            split_pk(ra[it][0].x, ra[it][0].y, h0, l0);
            split_pk(ra[it][0].z, ra[it][0].w, h1, l1);
            split_pk(ra[it][1].x, ra[it][1].y, h2, l2);
            split_pk(ra[it][1].z, ra[it][1].w, h3, l3);
            S4[0][u] = make_uint4(h0, h1, h2, h3);
            S4[1][u] = make_uint4(l0, l1, l2, l3);
            split_pk(rb[it][0].x, rb[it][0].y, h0, l0);
            split_pk(rb[it][0].z, rb[it][0].w, h1, l1);
            split_pk(rb[it][1].x, rb[it][1].y, h2, l2);
            split_pk(rb[it][1].z, rb[it][1].w, h3, l3);
            S4[2][u] = make_uint4(h0, h1, h2, h3);
            S4[3][u] = make_uint4(l0, l1, l2, l3);
        }
        __syncthreads();
        #pragma unroll
        for (int ksi = 0; ksi < 4; ksi++) {
            const int ks = ksi * 16;
            uint32_t ah[4], al[4], bh0[4], bh1[4], bl0[4], bl1[4];
            int ra_ = m0 + (lane & 15), ca = (ks >> 3) + (lane >> 4);
            uint32_t aoff = (uint32_t)(ra_ * 8 + (ca ^ (ra_ & 7))) * 16;
            ldsm4(ah, base + aoff);
            ldsm4(al, base + 8192 + aoff);
            int rb_ = ks + (lane & 15);
            int cb0 = (nw0 >> 3) + (lane >> 4), cb1 = ((nw0 + 16) >> 3) + (lane >> 4);
            uint32_t b0off = (uint32_t)(rb_ * 8 + (cb0 ^ (rb_ & 7))) * 16;
            uint32_t b1off = (uint32_t)(rb_ * 8 + (cb1 ^ (rb_ & 7))) * 16;
            ldsm4t(bh0, base + 16384 + b0off);
            ldsm4t(bh1, base + 16384 + b1off);
            ldsm4t(bl0, base + 24576 + b0off);
            ldsm4t(bl1, base + 24576 + b1off);
            mma16816(acc[0], ah, bh0[0], bh0[1]);
            mma16816(acc[0], ah, bl0[0], bl0[1]);
            mma16816(acc[0], al, bh0[0], bh0[1]);
            mma16816(acc[1], ah, bh0[2], bh0[3]);
            mma16816(acc[1], ah, bl0[2], bl0[3]);
            mma16816(acc[1], al, bh0[2], bh0[3]);
            mma16816(acc[2], ah, bh1[0], bh1[1]);
            mma16816(acc[2], ah, bl1[0], bl1[1]);
            mma16816(acc[2], al, bh1[0], bh1[1]);
            mma16816(acc[3], ah, bh1[2], bh1[3]);
            mma16816(acc[3], ah, bl1[2], bl1[3]);
            mma16816(acc[3], al, bh1[2], bh1[3]);
        }
    }
    size_t zo = (size_t)blockIdx.z * Bn * Un;
    const int g = lane >> 2, tg = lane & 3;
    #pragma unroll
    for (int j = 0; j < 4; j++) {
        int ncol = n0 + nw0 + j * 8 + tg * 2;
        int m_lo = m0 + g, m_hi = m0 + g + 8;
        *(float2*)&kpart[zo + (size_t)m_lo * Un + ncol] = make_float2(acc[j][0], acc[j][1]);
        *(float2*)&kpart[zo + (size_t)m_hi * Un + ncol] = make_float2(acc[j][2], acc[j][3]);
    }
}

// -------- rw softmax: 2 warps per (b,h) row, 4 rows per CTA --------
__global__ __launch_bounds__(256) void k_softmax513(const float* __restrict__ logitT,
                                                    float* __restrict__ probT,
                                                    const float* __restrict__ A,
                                                    float* __restrict__ cArr, int l) {
    __shared__ float smx[4][2], ssum[4][2], sdot[4][2];
    constexpr int IT = 9;
    int t = threadIdx.x, w = t >> 5, lane = t & 31;
    int r = w >> 1, half = w & 1;
    int gw = blockIdx.x * 4 + r;
    pdl_wait();
    const float* basep = logitT + (size_t)gw * SLP;
    float vals[IT];
    float mx = -1e30f;
    #pragma unroll
    for (int i = 0; i < IT; i++) {
        int s = half * 256 + i * 32 + lane;
        bool ok = half ? (s < NSLOT) : (i < 8);
        float v = ok ? (basep[s] + basep[LOGZ + s]) : -1e30f;
        vals[i] = v;
        mx = fmaxf(mx, v);
    }
    #pragma unroll
    for (int o = 16; o; o >>= 1) mx = fmaxf(mx, __shfl_xor_sync(0xffffffffu, mx, o));
    if (lane == 0) smx[r][half] = mx;
    __syncthreads();
    mx = fmaxf(smx[r][0], smx[r][1]);
    float sum = 0.f;
    #pragma unroll
    for (int i = 0; i < IT; i++) {
        int s = half * 256 + i * 32 + lane;
        bool ok = half ? (s < NSLOT) : (i < 8);
        float e = ok ? __expf(vals[i] - mx) : 0.f;
        vals[i] = e;
        sum += e;
    }
    #pragma unroll
    for (int o = 16; o; o >>= 1) sum += __shfl_xor_sync(0xffffffffu, sum, o);
    if (lane == 0) ssum[r][half] = sum;
    __syncthreads();
    float inv = 1.f / (ssum[r][0] + ssum[r][1]);
    float* dst = probT + (size_t)gw * SLP;
    #pragma unroll
    for (int i = 0; i < IT; i++) {
        int s = half * 256 + i * 32 + lane;
        bool ok = half ? (s < NSLOT) : (i < 8);
        if (ok) dst[s] = vals[i] * inv;
    }
    // mean of memory-slot weights (m<512): rw or rw*A
    float dot = 0.f;
    const float* ap = A + (size_t)gw * BHR;
    #pragma unroll
    for (int i = 0; i < 8; i++) {
        int m = half * 256 + i * 32 + lane;
        float pv = vals[i] * inv;
        dot += (l > 0) ? pv * ap[m] : pv;
    }
    #pragma unroll
    for (int o = 16; o; o >>= 1) dot += __shfl_xor_sync(0xffffffffu, dot, o);
    if (lane == 0) sdot[r][half] = dot;
    __syncthreads();
    if (half == 0 && lane == 0)
        cArr[gw] = (sdot[r][0] + sdot[r][1]) * (1.f / 512.f);
}

// -------- fused ww-softmax (2 halves) + coefficient recurrence --------
__global__ __launch_bounds__(128) void k_smcoef(const float* __restrict__ wlogT,
                                                float* __restrict__ A,
                                                float* __restrict__ wA,
                                                float* __restrict__ B,
                                                float* __restrict__ sB, int l) {
    __shared__ float redm[4], reds[4], wred[4][4];
    int row = blockIdx.x;
    int t = threadIdx.x;
    int w = t >> 5, lane = t & 31;
    pdl_wait();

    float4 lg  = ((const float4*)(wlogT + (size_t)row*SLP))[t];
    float4 lg1 = ((const float4*)(wlogT + LOGZ + (size_t)row*SLP))[t];
    lg.x += lg1.x; lg.y += lg1.y; lg.z += lg1.z; lg.w += lg1.w;
    float mx = fmaxf(fmaxf(lg.x, lg.y), fmaxf(lg.z, lg.w));
    #pragma unroll
    for (int o = 16; o; o >>= 1) mx = fmaxf(mx, __shfl_xor_sync(0xffffffffu, mx, o));
    if (lane == 0) redm[w] = mx;
    __syncthreads();
    mx = fmaxf(fmaxf(redm[0], redm[1]), fmaxf(redm[2], redm[3]));
    float4 e = make_float4(__expf(lg.x - mx), __expf(lg.y - mx),
                           __expf(lg.z - mx), __expf(lg.w - mx));
    float s = e.x + e.y + e.z + e.w;
    #pragma unroll
    for (int o = 16; o; o >>= 1) s += __shfl_xor_sync(0xffffffffu, s, o);
    if (lane == 0) reds[w] = s;
    __syncthreads();
    float inv = 1.f / (reds[0] + reds[1] + reds[2] + reds[3]);
    float4 ww = make_float4(e.x * inv, e.y * inv, e.z * inv, e.w * inv);

    float4 om = make_float4(1.f-ww.x, 1.f-ww.y, 1.f-ww.z, 1.f-ww.w);
    float4 aold;
    if (l == 0) aold = make_float4(1.f, 1.f, 1.f, 1.f);
    else        aold = ((const float4*)(A + (size_t)row*BHR))[t];
    if (l < 3) {
        ((float4*)(wA + (size_t)row*BHR))[t] =
            make_float4(aold.x*ww.x, aold.y*ww.y, aold.z*ww.z, aold.w*ww.w);
    }
    ((float4*)(A + (size_t)row*BHR))[t] =
        make_float4(aold.x*om.x, aold.y*om.y, aold.z*om.z, aold.w*om.w);
    float sums[4] = {0.f, 0.f, 0.f, 0.f};
    for (int j = 0; j < l; j++) {
        float4* bp = (float4*)(B + (size_t)j*BSTR + (size_t)row*BHR);
        float4 bv = bp[t];
        bv.x *= om.x; bv.y *= om.y; bv.z *= om.z; bv.w *= om.w;
        bp[t] = bv;
        sums[j] = bv.x + bv.y + bv.z + bv.w;
    }
    ((float4*)(B + (size_t)l*BSTR + (size_t)row*BHR))[t] = ww;
    sums[l] = ww.x + ww.y + ww.z + ww.w;
    for (int j = 0; j <= l; j++) {
        float ss = sums[j];
        #pragma unroll
        for (int o = 16; o; o >>= 1) ss += __shfl_xor_sync(0xffffffffu, ss, o);
        if (lane == 0) wred[w][j] = ss;
    }
    __syncthreads();
    if (t == 0) {
        for (int j = 0; j <= l; j++)
            sB[j*Bn*Hn + row] = wred[0][j] + wred[1][j] + wred[2][j] + wred[3][j];
    }
}

// -------- initial: fp32 slot-sum partials + bf16 conversion --------
__global__ __launch_bounds__(256) void k_convsum(const float* __restrict__ mem,
                                                 __nv_bfloat16* __restrict__ memh,
                                                 float* __restrict__ part) {
    int b = blockIdx.x, c = blockIdx.y, t = threadIdx.x;
    pdl_wait();
    size_t base = (size_t)(b*Mn + c*MCH)*U4 + t;
    const float4* m4 = (const float4*)mem + base;
    uint2* o2 = (uint2*)memh + base;
    float ax=0.f, ay=0.f, az=0.f, aw=0.f;
    #pragma unroll 8
    for (int i = 0; i < MCH; i++) {
        float4 v = __ldcs(m4 + (size_t)i*U4);
        ax += v.x; ay += v.y; az += v.z; aw += v.w;
        __nv_bfloat162 p0 = __floats2bfloat162_rn(v.x, v.y);
        __nv_bfloat162 p1 = __floats2bfloat162_rn(v.z, v.w);
        o2[(size_t)i*U4] = make_uint2(*reinterpret_cast<uint32_t*>(&p0),
                                      *reinterpret_cast<uint32_t*>(&p1));
    }
    ((float4*)part)[(b*NCH + c)*U4 + t] = make_float4(ax, ay, az, aw);
}

// -------- mean-subtracted weighted pass over bf16 mem --------
__global__ __launch_bounds__(256) void k_wpass(const __nv_bfloat16* __restrict__ memh,
                                               const float* __restrict__ rwT,
                                               const float* __restrict__ A,
                                               const float* __restrict__ cArr,
                                               float* __restrict__ part, int l) {
    __shared__ float ws[MCH][17];
    int b = blockIdx.x, c = blockIdx.y, t = threadIdx.x;
    pdl_wait();
    #pragma unroll
    for (int it = 0; it < 2; it++) {
        int idx = t + 256 * it;
        int hh = idx >> 5, s = idx & 31;
        int m = c * MCH + s;
        float v = rwT[(size_t)(b*Hn + hh)*SLP + m];
        if (l > 0) v *= A[(size_t)(b*Hn + hh)*BHR + m];
        ws[s][hh] = v - cArr[b*Hn + hh];
    }
    __syncthreads();
    int h = t >> 4;
    const uint2* m2 = (const uint2*)memh + (size_t)(b*Mn + c*MCH)*U4 + t;
    float ax=0.f, ay=0.f, az=0.f, aw=0.f;
    #pragma unroll 8
    for (int i = 0; i < MCH; i++) {
        float4 v = bfu2_to_f4(m2[(size_t)i*U4]);
        float wv = ws[i][h];
        ax += wv*v.x; ay += wv*v.y; az += wv*v.z; aw += wv*v.w;
    }
    ((float4*)part)[(b*NCH + c)*U4 + t] = make_float4(ax, ay, az, aw);
}

// -------- T pass over bf16 mem --------
__global__ __launch_bounds__(256) void k_tpass(const __nv_bfloat16* __restrict__ memh,
                                               const float* __restrict__ wA,
                                               float* __restrict__ part) {
    __shared__ float ws[MCH][17];
    int b = blockIdx.x, c = blockIdx.y, t = threadIdx.x;
    pdl_wait();
    #pragma unroll
    for (int it = 0; it < 2; it++) {
        int idx = t + 256 * it;
        int hh = idx >> 5, s = idx & 31;
        ws[s][hh] = wA[(size_t)(b*Hn + hh)*BHR + c*MCH + s];
    }
    __syncthreads();
    int h = t >> 4;
    const uint2* m2 = (const uint2*)memh + (size_t)(b*Mn + c*MCH)*U4 + t;
    float ax=0.f, ay=0.f, az=0.f, aw=0.f;
    #pragma unroll 8
    for (int i = 0; i < MCH; i++) {
        float4 v = bfu2_to_f4(m2[(size_t)i*U4]);
        float wv = ws[i][h];
        ax += wv*v.x; ay += wv*v.y; az += wv*v.z; aw += wv*v.w;
    }
    ((float4*)part)[(b*NCH + c)*U4 + t] = make_float4(ax, ay, az, aw);
}

// -------- S update + memstate (captures fp32 SlotSum at l=0) --------
__global__ __launch_bounds__(256) void k_state(const float* __restrict__ part,
                                               float* __restrict__ S,
                                               float* __restrict__ slot,
                                               const float* __restrict__ nv,
                                               const float* __restrict__ sB,
                                               const float* __restrict__ prev,
                                               float* __restrict__ state, int l) {
    int b = blockIdx.x, t = threadIdx.x, h = t >> 4;
    pdl_wait();
    float4 p = make_float4(0.f, 0.f, 0.f, 0.f);
    #pragma unroll
    for (int c = 0; c < NCH; c++) {
        float4 v = ((const float4*)part)[(b*NCH + c)*U4 + t];
        p.x += v.x; p.y += v.y; p.z += v.z; p.w += v.w;
    }
    float4 s;
    if (l == 0) {
        s = p;
        ((float4*)slot)[b*U4 + t] = p;
    } else {
        s = ((const float4*)S)[b*U4 + t];
        s.x -= p.x; s.y -= p.y; s.z -= p.z; s.w -= p.w;
    }
    ((float4*)S)[b*U4 + t] = s;
    float4 a = ((const float4*)prev)[b*U4 + t];
    a.x += s.x; a.y += s.y; a.z += s.z; a.w += s.w;
    for (int j = 0; j < l; j++) {
        float cf = sB[j*Bn*Hn + b*Hn + h];
        float4 n = ((const float4*)nv)[j*NV4 + b*U4 + t];
        a.x += cf*n.x; a.y += cf*n.y; a.z += cf*n.z; a.w += cf*n.w;
    }
    const float inv = 1.f / 513.f;
    a.x *= inv; a.y *= inv; a.z *= inv; a.w *= inv;
    ((float4*)state)[b*U4 + t] = a;
}

// -------- read finalize --------
__global__ __launch_bounds__(256) void k_readfin(const float* __restrict__ part,
                                                 const float* __restrict__ rwT,
                                                 const float* __restrict__ B,
                                                 const float* __restrict__ nv,
                                                 const float* __restrict__ prev,
                                                 const float* __restrict__ slot,
                                                 const float* __restrict__ cArr,
                                                 float* __restrict__ readv, int l) {
    __shared__ float sRB[3][16];
    int b = blockIdx.x, t = threadIdx.x;
    int w = t >> 5, lane = t & 31;
    pdl_wait();
    for (int task = w; task < l * 16; task += 8) {
        int j = task >> 4, h = task & 15;
        const float* rwp = rwT + (size_t)(b*Hn + h)*SLP;
        const float* bp  = B + (size_t)j*BSTR + (size_t)(b*Hn + h)*BHR;
        float s = 0.f;
        #pragma unroll
        for (int i = 0; i < 16; i++) s += rwp[lane + 32*i] * bp[lane + 32*i];
        #pragma unroll
        for (int o = 16; o; o >>= 1) s += __shfl_xor_sync(0xffffffffu, s, o);
        if (lane == 0) sRB[j][h] = s;
    }
    __syncthreads();
    int h = t >> 4;
    float cc = cArr[b*Hn + h];
    float4 sl = ((const float4*)slot)[b*U4 + t];
    float4 a = make_float4(cc*sl.x, cc*sl.y, cc*sl.z, cc*sl.w);
    #pragma unroll
    for (int c = 0; c < NCH; c++) {
        float4 v = ((const float4*)part)[(b*NCH + c)*U4 + t];
        a.x += v.x; a.y += v.y; a.z += v.z; a.w += v.w;
    }
    for (int j = 0; j < l; j++) {
        float cf = sRB[j][h];
        float4 n = ((const float4*)nv)[j*NV4 + b*U4 + t];
        a.x += cf*n.x; a.y += cf*n.y; a.z += cf*n.z; a.w += cf*n.w;
    }
    float wl = rwT[(size_t)(b*Hn + h)*SLP + Mn];
    float4 pv = ((const float4*)prev)[b*U4 + t];
    a.x += wl*pv.x; a.y += wl*pv.y; a.z += wl*pv.z; a.w += wl*pv.w;
    ((float4*)readv)[b*U4 + t] = a;
}

// -------- combine K-split (x8) + bias + relu --------
__global__ __launch_bounds__(256) void k_wk_reduce(const float* __restrict__ part,
                                                   const float* __restrict__ bk,
                                                   float* __restrict__ nvout,
                                                   float* __restrict__ out2) {
    int b = blockIdx.x, t = threadIdx.x;
    pdl_wait();
    float4 a = ((const float4*)bk)[t];
    #pragma unroll
    for (int z = 0; z < KZ; z++) {
        float4 v = ((const float4*)part)[((size_t)z*Bn + b)*U4 + t];
        a.x += v.x; a.y += v.y; a.z += v.z; a.w += v.w;
    }
    a.x = fmaxf(a.x, 0.f); a.y = fmaxf(a.y, 0.f);
    a.z = fmaxf(a.z, 0.f); a.w = fmaxf(a.w, 0.f);
    ((float4*)nvout)[b*U4 + t] = a;
    if (out2) ((float4*)out2)[b*U4 + t] = a;
}

// -------- final reconstruction (fp32 mem0) --------
__global__ __launch_bounds__(256) void k_recon(const float* __restrict__ mem,
                                               const float* __restrict__ A,
                                               const float* __restrict__ B,
                                               const float* __restrict__ nv,
                                               float* __restrict__ outm) {
    __shared__ float sA[MCH][17];
    __shared__ float sBs[4][MCH][17];
    int b = blockIdx.x, c = blockIdx.y, t = threadIdx.x;
    pdl_wait();
    #pragma unroll
    for (int it = 0; it < 2; it++) {
        int idx = t + 256 * it;
        int hh = idx >> 5, s = idx & 31;
        size_t ro = (size_t)(b*Hn + hh)*BHR + c*MCH + s;
        sA[s][hh] = A[ro];
        #pragma unroll
        for (int j = 0; j < 4; j++) sBs[j][s][hh] = B[(size_t)j*BSTR + ro];
    }
    __syncthreads();
    int h = t >> 4;
    float4 n0 = ((const float4*)nv)[0*NV4 + b*U4 + t];
    float4 n1 = ((const float4*)nv)[1*NV4 + b*U4 + t];
    float4 n2 = ((const float4*)nv)[2*NV4 + b*U4 + t];
    float4 n3 = ((const float4*)nv)[3*NV4 + b*U4 + t];
    size_t basei = (size_t)(b*Mn + c*MCH)*U4 + t;
    const float4* mi = (const float4*)mem;
    float4* mo = (float4*)outm;
    #pragma unroll 4
    for (int i = 0; i < MCH; i++) {
        float4 v = __ldcs(mi + basei + (size_t)i*U4);
        float a  = sA[i][h];
        float b0 = sBs[0][i][h], b1 = sBs[1][i][h], b2 = sBs[2][i][h], b3 = sBs[3][i][h];
        float4 r;
        r.x = a*v.x + b0*n0.x + b1*n1.x + b2*n2.x + b3*n3.x;
        r.y = a*v.y + b0*n0.y + b1*n1.y + b2*n2.y + b3*n3.y;
        r.z = a*v.z + b0*n0.z + b1*n1.z + b2*n2.z + b3*n3.z;
        r.w = a*v.w + b0*n0.w + b1*n1.w + b2*n2.w + b3*n3.w;
        mo[basei + (size_t)i*U4] = r;
    }
}

// -------- host: PDL launch helper --------
template <typename F, typename... Args>
static inline void pdl(F kern, dim3 grid, dim3 blk, Args... args) {
    cudaLaunchConfig_t cfg = {};
    cfg.gridDim = grid;
    cfg.blockDim = blk;
    cudaLaunchAttribute attr = {};
    attr.id = cudaLaunchAttributeProgrammaticStreamSerialization;
    attr.val.programmaticStreamSerializationAllowed = 1;
    cfg.attrs = &attr;
    cfg.numAttrs = 1;
    cudaLaunchKernelEx(&cfg, kern, args...);
}

// -------- host orchestration --------
extern "C" void kernel_launch(void* const* d_in, const int* in_sizes, int n_in,
                              void* d_out, int out_size) {
    const float* x      = (const float*)d_in[0];
    const float* mem0   = (const float*)d_in[1];
    const float* Wr     = (const float*)d_in[2];
    const float* br     = (const float*)d_in[3];
    const float* Ww     = (const float*)d_in[4];
    const float* bw     = (const float*)d_in[5];
    const float* Wk     = (const float*)d_in[6];
    const float* bk     = (const float*)d_in[7];
    float* outp    = (float*)d_out;
    float* out_mem = outp + Bn*Un;

    float *p_part, *p_S, *p_slot, *p_state, *p_rlogT, *p_rwT, *p_wlogT, *p_c;
    float *p_read, *p_nv, *p_kpart, *p_A, *p_wA, *p_B, *p_sB;
    __nv_bfloat16* p_memh;
    cudaGetSymbolAddress((void**)&p_memh,  g_memh);
    cudaGetSymbolAddress((void**)&p_part,  g_part);
    cudaGetSymbolAddress((void**)&p_S,     g_S);
    cudaGetSymbolAddress((void**)&p_slot,  g_slot);
    cudaGetSymbolAddress((void**)&p_state, g_state);
    cudaGetSymbolAddress((void**)&p_rlogT, g_rlogT);
    cudaGetSymbolAddress((void**)&p_rwT,   g_rwT);
    cudaGetSymbolAddress((void**)&p_wlogT, g_wlogT);
    cudaGetSymbolAddress((void**)&p_c,     g_cmean);
    cudaGetSymbolAddress((void**)&p_read,  g_read);
    cudaGetSymbolAddress((void**)&p_nv,    g_nv);
    cudaGetSymbolAddress((void**)&p_kpart, g_kpart);
    cudaGetSymbolAddress((void**)&p_A,     g_A);
    cudaGetSymbolAddress((void**)&p_wA,    g_wA);
    cudaGetSymbolAddress((void**)&p_B,     g_B);
    cudaGetSymbolAddress((void**)&p_sB,    g_sB);

    dim3 blk(256);
    pdl(k_convsum, dim3(Bn, NCH), blk,
        mem0, (__nv_bfloat16*)p_memh, (float*)p_part);

    const float* prev = x;
    for (int l = 0; l < Dn; l++) {
        float* nv_l = p_nv + (size_t)l * Bn * Un;

        pdl(k_state, dim3(Bn), blk,
            (const float*)p_part, p_S, p_slot, (const float*)p_nv,
            (const float*)p_sB, prev, p_state, l);
        pdl(k_gemm_bf16T, dim3(129, 1, 2), blk,
            (const float*)p_state, Wr + (size_t)l*Un*NRr, br + (size_t)l*NRr,
            p_rlogT, (int)NRr, 8);
        pdl(k_softmax513, dim3(256), dim3(256),
            (const float*)p_rlogT, p_rwT, (const float*)p_A, p_c, l);

        pdl(k_wpass, dim3(Bn, NCH), blk,
            (const __nv_bfloat16*)p_memh, (const float*)p_rwT, (const float*)p_A,
            (const float*)p_c, p_part, l);
        pdl(k_readfin, dim3(Bn), blk,
            (const float*)p_part, (const float*)p_rwT, (const float*)p_B,
            (const float*)p_nv, prev, (const float*)p_slot, (const float*)p_c,
            p_read, l);

        pdl(k_gemm_x3, dim3(16, 1, KZ), blk,
            (const float*)p_read, Wk + (size_t)l*Un*Un, p_kpart);
        pdl(k_wk_reduce, dim3(Bn), blk,
            (const float*)p_kpart, bk + (size_t)l*Un, nv_l,
            (l == Dn-1) ? outp : (float*)nullptr);

        pdl(k_gemm_bf16T, dim3(128, 1, 2), blk,
            (const float*)nv_l, Ww + (size_t)l*Un*NWw, bw + (size_t)l*NWw,
            p_wlogT, (int)NWw, 8);
        pdl(k_smcoef, dim3(Bn*Hn), dim3(128),
            (const float*)p_wlogT, p_A, p_wA, p_B, p_sB, l);

        if (l < Dn - 1)
            pdl(k_tpass, dim3(Bn, NCH), blk,
                (const __nv_bfloat16*)p_memh, (const float*)p_wA, p_part);

        prev = nv_l;
    }

    pdl(k_recon, dim3(Bn, NCH), blk,
        mem0, (const float*)p_A, (const float*)p_B, (const float*)p_nv, out_mem);
}